// round 15
// baseline (speedup 1.0000x reference)
#include <cuda_runtime.h>
#include <cuda_fp16.h>
#include <cstdint>
#include <math.h>

#define NMAX 50000
#define EMAX 800000
#define DIM  128
#define LNUM 3

// ---------------------------------------------------------------------------
// scratch (no allocation allowed)
// ---------------------------------------------------------------------------
__device__ __half g_hh [(size_t)NMAX * DIM];        // fp16 activations between layers (and x)
__device__ __half g_c  [(size_t)NMAX * DIM];        // GIN combine (GEMM1 input)
__device__ __half g_z  [(size_t)NMAX * 2 * DIM];    // z (GEMM2 input)
__device__ float g_s1[LNUM * 2 * DIM];
__device__ float g_t1[LNUM * 2 * DIM];
__device__ float g_so[(LNUM - 1) * DIM];
__device__ float g_to[(LNUM - 1) * DIM];
// transposed fp16 weights: W1T [L][256][128], W2T [L][128][256]
__device__ __half g_w1[LNUM * 2 * DIM * DIM];
__device__ __half g_w2[LNUM * 2 * DIM * DIM];
// CSR
__device__ int g_rowptr[NMAX + 1];
__device__ int g_cursor[NMAX];
__device__ int g_adj[EMAX];
__device__ int g_part[64];          // scan partials (<=49 blocks)

// ---------------------------------------------------------------------------
// helpers
// ---------------------------------------------------------------------------
__device__ __forceinline__ uint32_t smem_to_u32(const void* p) {
    uint32_t a;
    asm("{ .reg .u64 t; cvta.to.shared.u64 t, %1; cvt.u32.u64 %0, t; }" : "=r"(a) : "l"(p));
    return a;
}
__device__ __forceinline__ void ldmx4(uint32_t* r, uint32_t addr) {
    asm volatile("ldmatrix.sync.aligned.m8n8.x4.shared.b16 {%0,%1,%2,%3}, [%4];"
                 : "=r"(r[0]), "=r"(r[1]), "=r"(r[2]), "=r"(r[3]) : "r"(addr));
}
__device__ __forceinline__ void mma_f16(float* c, const uint32_t* a, uint32_t b0, uint32_t b1) {
    asm volatile("mma.sync.aligned.m16n8k16.row.col.f32.f16.f16.f32 "
                 "{%0,%1,%2,%3}, {%4,%5,%6,%7}, {%8,%9}, {%0,%1,%2,%3};"
                 : "+f"(c[0]), "+f"(c[1]), "+f"(c[2]), "+f"(c[3])
                 : "r"(a[0]), "r"(a[1]), "r"(a[2]), "r"(a[3]), "r"(b0), "r"(b1));
}
__device__ __forceinline__ void cp16(uint32_t saddr, const void* gptr) {
    asm volatile("cp.async.cg.shared.global [%0], [%1], 16;" :: "r"(saddr), "l"(gptr));
}
#define CP_COMMIT() asm volatile("cp.async.commit_group;" ::: "memory")
#define CP_WAIT1()  asm volatile("cp.async.wait_group 1;" ::: "memory")

// accumulate 8 halfs (one uint4) into 8 fp32 accumulators
__device__ __forceinline__ void acc8(float* s, uint4 r) {
    float2 p;
    p = __half22float2(*(__half2*)&r.x); s[0] += p.x; s[1] += p.y;
    p = __half22float2(*(__half2*)&r.y); s[2] += p.x; s[3] += p.y;
    p = __half22float2(*(__half2*)&r.z); s[4] += p.x; s[5] += p.y;
    p = __half22float2(*(__half2*)&r.w); s[6] += p.x; s[7] += p.y;
}

// ---------------------------------------------------------------------------
// Fused setup: BN fold + x->fp16 + weight transpose/round.  One launch.
// ---------------------------------------------------------------------------
__global__ void setup_kernel(const float* __restrict__ x, __half* __restrict__ xh, int nx2,
                             const float* __restrict__ W1, const float* __restrict__ W2,
                             __half* __restrict__ w1, __half* __restrict__ w2, int wtot,
                             const float* __restrict__ g1, const float* __restrict__ be1,
                             const float* __restrict__ m1, const float* __restrict__ v1,
                             const float* __restrict__ go, const float* __restrict__ bo,
                             const float* __restrict__ mo, const float* __restrict__ vo,
                             float* __restrict__ s1, float* __restrict__ t1,
                             float* __restrict__ so, float* __restrict__ to)
{
    int i = blockIdx.x * blockDim.x + threadIdx.x;
    if (i < nx2) {
        float2 v = *((const float2*)x + i);
        __half2 p = __floats2half2_rn(v.x, v.y);
        *((__half2*)xh + i) = p;
    }
    if (i < wtot) {
        int l = i / (2 * DIM * DIM);
        int rem = i % (2 * DIM * DIM);
        {
            int n = rem / DIM, k = rem % DIM;
            w1[i] = __float2half_rn(W1[(size_t)l * DIM * 2 * DIM + (size_t)k * 2 * DIM + n]);
        }
        {
            int n2 = rem / (2 * DIM), k2 = rem % (2 * DIM);
            w2[i] = __float2half_rn(W2[(size_t)l * 2 * DIM * DIM + (size_t)k2 * DIM + n2]);
        }
    }
    if (i < LNUM * 2 * DIM) {
        float sc = g1[i] * rsqrtf(v1[i] + 1e-5f);
        s1[i] = sc;
        t1[i] = be1[i] - m1[i] * sc;
    }
    if (i < (LNUM - 1) * DIM) {
        float sc = go[i] * rsqrtf(vo[i] + 1e-5f);
        so[i] = sc;
        to[i] = bo[i] - mo[i] * sc;
    }
}

// ---------------------------------------------------------------------------
// CSR build: memset -> hist -> 2-level parallel scan -> fill
// ---------------------------------------------------------------------------
__global__ void hist_kernel(const int* __restrict__ dst, int* __restrict__ cnt, int E)
{
    int e = blockIdx.x * blockDim.x + threadIdx.x;
    if (e < E) atomicAdd(&cnt[dst[e] + 1], 1);
}
__global__ void scan1_kernel(int* __restrict__ cnt, int* __restrict__ part, int n)
{
    __shared__ int wsum[32];
    int tid = threadIdx.x, lane = tid & 31, wid = tid >> 5;
    int i = blockIdx.x * 1024 + tid;
    int v = (i < n) ? cnt[i] : 0;
    int s = v;
#pragma unroll
    for (int o = 1; o < 32; o <<= 1) {
        int t = __shfl_up_sync(0xffffffffu, s, o);
        if (lane >= o) s += t;
    }
    if (lane == 31) wsum[wid] = s;
    __syncthreads();
    if (wid == 0) {
        int w = wsum[lane];
#pragma unroll
        for (int o = 1; o < 32; o <<= 1) {
            int t = __shfl_up_sync(0xffffffffu, w, o);
            if (lane >= o) w += t;
        }
        wsum[lane] = w;
    }
    __syncthreads();
    int inc = s + (wid ? wsum[wid - 1] : 0);
    if (i < n) cnt[i] = inc;
    if (tid == 1023) part[blockIdx.x] = inc;
}
__global__ void scan2_kernel(int* __restrict__ part, int nb)
{
    int tid = threadIdx.x;            // 0..63
    int lane = tid & 31;
    int wid = tid >> 5;
    int v = (tid < nb) ? part[tid] : 0;
    int s = v;
#pragma unroll
    for (int o = 1; o < 32; o <<= 1) {
        int t = __shfl_up_sync(0xffffffffu, s, o);
        if (lane >= o) s += t;
    }
    __shared__ int w0tot;
    if (tid == 31) w0tot = s;
    __syncthreads();
    if (wid == 1) s += w0tot;
    if (tid < nb) part[tid] = s;
}
__global__ void scan3_kernel(int* __restrict__ cnt, const int* __restrict__ part,
                             int* __restrict__ cur, int n)
{
    int i = blockIdx.x * 1024 + threadIdx.x;
    if (i >= n) return;
    int v = cnt[i];
    if (blockIdx.x > 0) v += part[blockIdx.x - 1];
    cnt[i] = v;
    if (i < n - 1) cur[i] = v;
}
__global__ void fill_kernel(const int* __restrict__ src, const int* __restrict__ dst,
                            int* __restrict__ cur, int* __restrict__ adj, int E)
{
    int e = blockIdx.x * blockDim.x + threadIdx.x;
    if (e < E) {
        int pos = atomicAdd(&cur[dst[e]], 1);
        adj[pos] = src[e];
    }
}

// ---------------------------------------------------------------------------
// Gather (fp16 h) + GIN combine.  HALF-WARP per node: 2 nodes/warp, lane
// covers 8 dims via uint4 (16 lanes x 16B = 256B row).  ILP-4 over neighbors.
// ---------------------------------------------------------------------------
__global__ __launch_bounds__(256)
void gather_kernel(const __half* __restrict__ h, const int* __restrict__ rowptr,
                   const int* __restrict__ adj, const float* __restrict__ epsp,
                   __half* __restrict__ cbuf, int N)
{
    int wib = threadIdx.x >> 5;             // warp in block (0..7)
    int lane = threadIdx.x & 31;
    int half = lane >> 4;                   // 0 or 1
    int sl = lane & 15;                     // sub-lane within half-warp
    int node = (blockIdx.x * 8 + wib) * 2 + half;
    bool valid = node < N;
    unsigned hmask = half ? 0xffff0000u : 0x0000ffffu;
    int hbase = half << 4;

    int beg = 0, end = 0;
    if (valid) { beg = rowptr[node]; end = rowptr[node + 1]; }

    float a0[8], a1[8], a2[8], a3[8];
#pragma unroll
    for (int q = 0; q < 8; q++) { a0[q] = 0.f; a1[q] = 0.f; a2[q] = 0.f; a3[q] = 0.f; }

    for (int e = beg; e < end; e += 16) {
        int a = (e + sl < end) ? __ldg(adj + e + sl) : 0;
        int cnt = min(16, end - e);
        int j = 0;
        for (; j + 3 < cnt; j += 4) {
            int n0 = __shfl_sync(hmask, a, hbase + j);
            int n1 = __shfl_sync(hmask, a, hbase + j + 1);
            int n2 = __shfl_sync(hmask, a, hbase + j + 2);
            int n3 = __shfl_sync(hmask, a, hbase + j + 3);
            uint4 r0 = __ldg((const uint4*)(h + (size_t)n0 * DIM) + sl);
            uint4 r1 = __ldg((const uint4*)(h + (size_t)n1 * DIM) + sl);
            uint4 r2 = __ldg((const uint4*)(h + (size_t)n2 * DIM) + sl);
            uint4 r3 = __ldg((const uint4*)(h + (size_t)n3 * DIM) + sl);
            acc8(a0, r0);
            acc8(a1, r1);
            acc8(a2, r2);
            acc8(a3, r3);
        }
        for (; j < cnt; j++) {
            int n0 = __shfl_sync(hmask, a, hbase + j);
            uint4 r0 = __ldg((const uint4*)(h + (size_t)n0 * DIM) + sl);
            acc8(a0, r0);
        }
    }

    if (!valid) return;

    float epsv = 1.0f + epsp[0];
    uint4 hraw = __ldg((const uint4*)(h + (size_t)node * DIM) + sl);
    float hv[8];
    {
        float2 p;
        p = __half22float2(*(__half2*)&hraw.x); hv[0] = p.x; hv[1] = p.y;
        p = __half22float2(*(__half2*)&hraw.y); hv[2] = p.x; hv[3] = p.y;
        p = __half22float2(*(__half2*)&hraw.z); hv[4] = p.x; hv[5] = p.y;
        p = __half22float2(*(__half2*)&hraw.w); hv[6] = p.x; hv[7] = p.y;
    }
    float c[8];
#pragma unroll
    for (int q = 0; q < 8; q++)
        c[q] = fmaf(epsv, hv[q], (a0[q] + a1[q]) + (a2[q] + a3[q]));

    __half2 p01 = __floats2half2_rn(c[0], c[1]);
    __half2 p23 = __floats2half2_rn(c[2], c[3]);
    __half2 p45 = __floats2half2_rn(c[4], c[5]);
    __half2 p67 = __floats2half2_rn(c[6], c[7]);
    uint4 outp;
    outp.x = *(uint32_t*)&p01;
    outp.y = *(uint32_t*)&p23;
    outp.z = *(uint32_t*)&p45;
    outp.w = *(uint32_t*)&p67;
    *((uint4*)(cbuf + (size_t)node * DIM) + sl) = outp;
}

// ---------------------------------------------------------------------------
// FP16 mma.sync GEMM, cp.async 3-stage pipeline, ONE barrier per chunk.
//   Output: fp32 (Cf, + dosm=fused log_softmax when grid.x==1) or fp16 (Ch).
// ---------------------------------------------------------------------------
#define BK 32
#define ASTRIDE 40                 // fp16 per smem row (80 B, conflict-free)
#define ABUF_B (128 * ASTRIDE * 2) // 10240 B per buffer
#define STAGE_B (2 * ABUF_B)       // A, W
#define NSTAGE 3

__global__ __launch_bounds__(256)
void gemm_mma_kernel(const __half* __restrict__ A, const __half* __restrict__ W,
                     const float* __restrict__ bias, const float* __restrict__ bns,
                     const float* __restrict__ bnt,
                     float* __restrict__ Cf, __half* __restrict__ Ch,
                     int M, int K, int Nc, int relu, int dosm)
{
    extern __shared__ char smem[];
    __shared__ float smax[128][4];
    __shared__ float ssum[128][4];
    const int tid = threadIdx.x;
    const int lane = tid & 31, wid = tid >> 5;
    const int warpM = wid >> 2, warpN = wid & 3;
    const int rowBase = blockIdx.y * 128;
    const int colBase = blockIdx.x * 128;
    const uint32_t sbase = smem_to_u32(smem);

    const __half* asrc[2];
    const __half* wsrc[2];
    uint32_t adst[2], wdst[2];
#pragma unroll
    for (int i = 0; i < 2; i++) {
        int idx = tid + i * 256;
        int row = idx >> 2, q = idx & 3;
        int g = rowBase + row;
        if (g >= M) g = M - 1;            // clamp (garbage rows unused)
        asrc[i] = A + (size_t)g * K + q * 8;
        wsrc[i] = W + (size_t)(colBase + row) * K + q * 8;
        adst[i] = row * (ASTRIDE * 2) + q * 16;
        wdst[i] = ABUF_B + row * (ASTRIDE * 2) + q * 16;
    }

    float acc[4][4][4];
#pragma unroll
    for (int a = 0; a < 4; a++)
#pragma unroll
        for (int b = 0; b < 4; b++)
#pragma unroll
            for (int c = 0; c < 4; c++) acc[a][b][c] = 0.f;

    const int frow = lane & 15, fk = (lane >> 4) * 8;
    uint32_t offA[4], offB[2];
#pragma unroll
    for (int mf = 0; mf < 4; mf++)
        offA[mf] = ((warpM * 64 + mf * 16 + frow) * ASTRIDE + fk) * 2;
#pragma unroll
    for (int nb = 0; nb < 2; nb++)
        offB[nb] = ((warpN * 32 + nb * 16 + frow) * ASTRIDE + fk) * 2;

    const int nch = K / BK;

    // ---- prologue: issue stages 0,1 (groups 0,1) ----
#pragma unroll
    for (int pc = 0; pc < 2; pc++) {
        uint32_t sb = sbase + pc * STAGE_B;
        int koff = pc * BK;
#pragma unroll
        for (int i = 0; i < 2; i++) {
            cp16(sb + adst[i], asrc[i] + koff);
            cp16(sb + wdst[i], wsrc[i] + koff);
        }
        CP_COMMIT();
    }

    for (int c = 0; c < nch; c++) {
        CP_WAIT1();
        __syncthreads();   // stage c visible; stage c-1 fully retired

        if (c + 2 < nch) {
            uint32_t sb = sbase + ((c + 2) % NSTAGE) * STAGE_B;
            int koff = (c + 2) * BK;
#pragma unroll
            for (int i = 0; i < 2; i++) {
                cp16(sb + adst[i], asrc[i] + koff);
                cp16(sb + wdst[i], wsrc[i] + koff);
            }
            CP_COMMIT();
        } else {
            CP_COMMIT();   // empty group keeps wait accounting uniform
        }

        uint32_t bufA = sbase + (c % NSTAGE) * STAGE_B;
        uint32_t bufW = bufA + ABUF_B;
#pragma unroll
        for (int ks = 0; ks < 2; ks++) {
            uint32_t ar[4][4], bw[2][4];
#pragma unroll
            for (int mf = 0; mf < 4; mf++)
                ldmx4(ar[mf], bufA + offA[mf] + ks * 32);
#pragma unroll
            for (int nb = 0; nb < 2; nb++)
                ldmx4(bw[nb], bufW + offB[nb] + ks * 32);
#pragma unroll
            for (int mf = 0; mf < 4; mf++) {
#pragma unroll
                for (int nf = 0; nf < 4; nf++) {
                    int nb = nf >> 1, sel = nf & 1;
                    mma_f16(acc[mf][nf], ar[mf], bw[nb][sel], bw[nb][sel + 2]);
                }
            }
        }
    }

    // ---- epilogue ----
    const int g = lane >> 2, tig = lane & 3;
    float bj0[4], bj1[4], sj0[4], sj1[4], tj0[4], tj1[4];
#pragma unroll
    for (int nf = 0; nf < 4; nf++) {
        int col = colBase + warpN * 32 + nf * 8 + 2 * tig;
        bj0[nf] = bias[col];
        bj1[nf] = bias[col + 1];
        if (bns) {
            sj0[nf] = bns[col];  sj1[nf] = bns[col + 1];
            tj0[nf] = bnt[col];  tj1[nf] = bnt[col + 1];
        }
    }
#pragma unroll
    for (int mf = 0; mf < 4; mf++)
#pragma unroll
        for (int nf = 0; nf < 4; nf++)
#pragma unroll
            for (int half = 0; half < 2; half++) {
                float v0 = acc[mf][nf][half * 2 + 0] + bj0[nf];
                float v1 = acc[mf][nf][half * 2 + 1] + bj1[nf];
                if (bns) {
                    v0 = fmaf(v0, sj0[nf], tj0[nf]);
                    v1 = fmaf(v1, sj1[nf], tj1[nf]);
                }
                if (relu) { v0 = fmaxf(v0, 0.f); v1 = fmaxf(v1, 0.f); }
                acc[mf][nf][half * 2 + 0] = v0;
                acc[mf][nf][half * 2 + 1] = v1;
            }

    if (dosm) {
        __syncthreads();   // retire pipeline smem reads before smax/ssum reuse
        float rowmax[4][2];
#pragma unroll
        for (int mf = 0; mf < 4; mf++)
#pragma unroll
            for (int half = 0; half < 2; half++) {
                float mx = -1e30f;
#pragma unroll
                for (int nf = 0; nf < 4; nf++) {
                    mx = fmaxf(mx, acc[mf][nf][half * 2 + 0]);
                    mx = fmaxf(mx, acc[mf][nf][half * 2 + 1]);
                }
                mx = fmaxf(mx, __shfl_xor_sync(0xffffffffu, mx, 1));
                mx = fmaxf(mx, __shfl_xor_sync(0xffffffffu, mx, 2));
                int row = warpM * 64 + mf * 16 + g + half * 8;
                if (tig == 0) smax[row][warpN] = mx;
            }
        __syncthreads();
#pragma unroll
        for (int mf = 0; mf < 4; mf++)
#pragma unroll
            for (int half = 0; half < 2; half++) {
                int row = warpM * 64 + mf * 16 + g + half * 8;
                float mx = fmaxf(fmaxf(smax[row][0], smax[row][1]),
                                 fmaxf(smax[row][2], smax[row][3]));
                rowmax[mf][half] = mx;
                float se = 0.f;
#pragma unroll
                for (int nf = 0; nf < 4; nf++) {
                    se += expf(acc[mf][nf][half * 2 + 0] - mx);
                    se += expf(acc[mf][nf][half * 2 + 1] - mx);
                }
                se += __shfl_xor_sync(0xffffffffu, se, 1);
                se += __shfl_xor_sync(0xffffffffu, se, 2);
                if (tig == 0) ssum[row][warpN] = se;
            }
        __syncthreads();
#pragma unroll
        for (int mf = 0; mf < 4; mf++)
#pragma unroll
            for (int half = 0; half < 2; half++) {
                int row = warpM * 64 + mf * 16 + g + half * 8;
                int grow = rowBase + row;
                if (grow >= M) continue;
                float tot = ssum[row][0] + ssum[row][1] + ssum[row][2] + ssum[row][3];
                float lse = rowmax[mf][half] + logf(tot);
#pragma unroll
                for (int nf = 0; nf < 4; nf++) {
                    int col = colBase + warpN * 32 + nf * 8 + 2 * tig;
                    float2 o = make_float2(acc[mf][nf][half * 2 + 0] - lse,
                                           acc[mf][nf][half * 2 + 1] - lse);
                    *(float2*)(Cf + (size_t)grow * Nc + col) = o;
                }
            }
        return;
    }

#pragma unroll
    for (int mf = 0; mf < 4; mf++)
#pragma unroll
        for (int half = 0; half < 2; half++) {
            int row = rowBase + warpM * 64 + mf * 16 + g + half * 8;
            if (row >= M) continue;
#pragma unroll
            for (int nf = 0; nf < 4; nf++) {
                int col = colBase + warpN * 32 + nf * 8 + 2 * tig;
                float v0 = acc[mf][nf][half * 2 + 0];
                float v1 = acc[mf][nf][half * 2 + 1];
                if (Cf) {
                    *(float2*)(Cf + (size_t)row * Nc + col) = make_float2(v0, v1);
                } else {
                    __half2 p = __floats2half2_rn(v0, v1);
                    *(uint32_t*)(Ch + (size_t)row * Nc + col) = *(uint32_t*)&p;
                }
            }
        }
}

// ---------------------------------------------------------------------------
extern "C" void kernel_launch(void* const* d_in, const int* in_sizes, int n_in,
                              void* d_out, int out_size)
{
    const float* x    = (const float*)d_in[0];
    const int*   ei   = (const int*)  d_in[1];
    const float* W1   = (const float*)d_in[2];
    const float* b1   = (const float*)d_in[3];
    const float* g1   = (const float*)d_in[4];
    const float* be1  = (const float*)d_in[5];
    const float* m1   = (const float*)d_in[6];
    const float* v1   = (const float*)d_in[7];
    const float* W2   = (const float*)d_in[8];
    const float* b2   = (const float*)d_in[9];
    const float* eps  = (const float*)d_in[10];
    const float* go   = (const float*)d_in[11];
    const float* bo   = (const float*)d_in[12];
    const float* mo   = (const float*)d_in[13];
    const float* vo   = (const float*)d_in[14];

    int N = in_sizes[0] / DIM;
    int E = in_sizes[1] / 2;

    float *s1, *t1, *so, *to;
    __half *hh, *cb, *zb, *w1, *w2;
    int *rowptr, *cursor, *adj, *part;
    cudaGetSymbolAddress((void**)&hh,     g_hh);
    cudaGetSymbolAddress((void**)&cb,     g_c);
    cudaGetSymbolAddress((void**)&zb,     g_z);
    cudaGetSymbolAddress((void**)&s1,     g_s1);
    cudaGetSymbolAddress((void**)&t1,     g_t1);
    cudaGetSymbolAddress((void**)&so,     g_so);
    cudaGetSymbolAddress((void**)&to,     g_to);
    cudaGetSymbolAddress((void**)&w1,     g_w1);
    cudaGetSymbolAddress((void**)&w2,     g_w2);
    cudaGetSymbolAddress((void**)&rowptr, g_rowptr);
    cudaGetSymbolAddress((void**)&cursor, g_cursor);
    cudaGetSymbolAddress((void**)&adj,    g_adj);
    cudaGetSymbolAddress((void**)&part,   g_part);

    const int dynSmem = NSTAGE * STAGE_B;  // 61440 B
    cudaFuncSetAttribute(gemm_mma_kernel, cudaFuncAttributeMaxDynamicSharedMemorySize, dynSmem);

    const int* src = ei;
    const int* dst = ei + E;

    // ---- setup: one fused kernel + memset + CSR build ----
    int nx2  = N * DIM / 2;
    int wtot = LNUM * 2 * DIM * DIM;
    int smax_work = nx2 > wtot ? nx2 : wtot;
    setup_kernel<<<(smax_work + 255) / 256, 256>>>(x, hh, nx2, W1, W2, w1, w2, wtot,
                                                   g1, be1, m1, v1, go, bo, mo, vo,
                                                   s1, t1, so, to);
    int n1 = N + 1;
    int sblocks = (n1 + 1023) / 1024;
    cudaMemsetAsync(rowptr, 0, (size_t)n1 * sizeof(int));
    hist_kernel<<<(E + 255) / 256, 256>>>(dst, rowptr, E);
    scan1_kernel<<<sblocks, 1024>>>(rowptr, part, n1);
    scan2_kernel<<<1, 64>>>(part, sblocks);
    scan3_kernel<<<sblocks, 1024>>>(rowptr, part, cursor, n1);
    fill_kernel<<<(E + 255) / 256, 256>>>(src, dst, cursor, adj, E);

    int mblocks = (N + 127) / 128;
    int gblocks = (N + 15) / 16;   // 8 warps x 2 nodes per block

    for (int i = 0; i < LNUM; i++) {
        gather_kernel<<<gblocks, 256>>>(hh, rowptr, adj, eps + i, cb, N);

        dim3 grid1(2, mblocks);
        gemm_mma_kernel<<<grid1, 256, dynSmem>>>(cb,
                                                 w1 + (size_t)i * 2 * DIM * DIM,
                                                 b1 + (size_t)i * 2 * DIM,
                                                 s1 + (size_t)i * 2 * DIM,
                                                 t1 + (size_t)i * 2 * DIM,
                                                 nullptr, zb,
                                                 N, DIM, 2 * DIM, 1, 0);

        dim3 grid2(1, mblocks);
        if (i < LNUM - 1) {
            gemm_mma_kernel<<<grid2, 256, dynSmem>>>(zb,
                                                     w2 + (size_t)i * 2 * DIM * DIM,
                                                     b2 + (size_t)i * DIM,
                                                     so + (size_t)i * DIM,
                                                     to + (size_t)i * DIM,
                                                     nullptr, hh,
                                                     N, 2 * DIM, DIM, 1, 0);
        } else {
            gemm_mma_kernel<<<grid2, 256, dynSmem>>>(zb,
                                                     w2 + (size_t)i * 2 * DIM * DIM,
                                                     b2 + (size_t)i * DIM,
                                                     nullptr, nullptr,
                                                     (float*)d_out, nullptr,
                                                     N, 2 * DIM, DIM, 0, 1);
        }
    }
}